// round 5
// baseline (speedup 1.0000x reference)
#include <cuda_runtime.h>
#include <cuda_fp16.h>
#include <cstdint>

#define RR 8
#define NN 50000
#define EE 400000
#define DD 128
#define CC 16
#define BB 4
#define RE_TOT (RR*EE)   /* 3,200,000 */
#define RN (RR*NN)       /* 400,000   */
#define NP 50064         /* padded rows (>= 391*128 = 50048) */

// ---------------- scratch (static device globals; no allocs) ----------------
__device__ int    g_deg[RN];
__device__ int    g_off[RN];
__device__ int    g_cur[RN];
__device__ int    g_col[RE_TOT];
__device__ int    g_bsums[512];
__device__ float  g_inv[RN];
__device__ __align__(16) __half g_he [(size_t)RR*NN*DD];  // fp16 embeds copy
__device__ __align__(16) __half g_h  [(size_t)NP*DD];     // [NP][128]
__device__ __align__(16) __half g_M  [(size_t)NP*512];    // [NP][512] (k = b*128+i)
__device__ __align__(16) __half g_h1 [(size_t)NP*DD];     // [NP][128]
__device__ __align__(16) __half g_Z  [(size_t)NP*DD];     // [NP][128] (col = r*16+c)
__device__ uint2  g_Bf1[32*16*32];           // B frags gemm1: [ks][nt][lane]
__device__ uint2  g_BfY[8*8*32];             // B frags gemmZ

// ---------------- embeds fp32 -> fp16 ----------------
__global__ void k_cvt(const float* __restrict__ embeds){
    size_t i = (size_t)blockIdx.x*blockDim.x + threadIdx.x;
    const size_t tot = (size_t)RR*NN*DD/4;
    if (i < tot){
        float4 v = reinterpret_cast<const float4*>(embeds)[i];
        __half2 p0 = __floats2half2_rn(v.x, v.y);
        __half2 p1 = __floats2half2_rn(v.z, v.w);
        uint2 st; st.x = *(uint32_t*)&p0; st.y = *(uint32_t*)&p1;
        reinterpret_cast<uint2*>(g_he)[i] = st;
    }
}

// ---------------- degree ----------------
__global__ void k_deg(const int* __restrict__ edst){
    int i = blockIdx.x*blockDim.x + threadIdx.x;
    if (i < RE_TOT){
        int r = i / EE;
        atomicAdd(&g_deg[r*NN + edst[i]], 1);
    }
}

// ---------------- hierarchical exclusive scan over g_deg -> g_off (+inv) ----------------
__device__ __forceinline__ int warp_incl_scan(int v){
    int lane = threadIdx.x & 31;
    #pragma unroll
    for (int o = 1; o < 32; o <<= 1){
        int u = __shfl_up_sync(0xffffffffu, v, o);
        if (lane >= o) v += u;
    }
    return v;
}

__global__ void k_scan1(){   // 512 threads, 1024 elems/block; also emits g_inv
    __shared__ int ws[16];
    int t = threadIdx.x;
    int base = blockIdx.x*1024;
    int i0 = base + 2*t;
    int a = (i0   < RN) ? g_deg[i0]   : 0;
    int b = (i0+1 < RN) ? g_deg[i0+1] : 0;
    int s = a + b;
    int inc = warp_incl_scan(s);
    int lane = t & 31, w = t >> 5;
    if (lane == 31) ws[w] = inc;
    __syncthreads();
    if (t < 16){
        int v = ws[t];
        #pragma unroll
        for (int o = 1; o < 16; o <<= 1){
            int u = __shfl_up_sync(0x0000ffffu, v, o);
            if (t >= o) v += u;
        }
        ws[t] = v;
    }
    __syncthreads();
    int add = (w > 0) ? ws[w-1] : 0;
    int excl = add + inc - s;
    if (i0   < RN){ g_off[i0]   = excl;     g_inv[i0]   = 1.0f/fmaxf((float)a, 1.0f); }
    if (i0+1 < RN){ g_off[i0+1] = excl + a; g_inv[i0+1] = 1.0f/fmaxf((float)b, 1.0f); }
    if (t == 0) g_bsums[blockIdx.x] = ws[15];
}

__global__ void k_scan2(int nb){  // single block of 512
    __shared__ int ws[16];
    int t = threadIdx.x;
    int v = (t < nb) ? g_bsums[t] : 0;
    int inc = warp_incl_scan(v);
    int lane = t & 31, w = t >> 5;
    if (lane == 31) ws[w] = inc;
    __syncthreads();
    if (t < 16){
        int x = ws[t];
        #pragma unroll
        for (int o = 1; o < 16; o <<= 1){
            int u = __shfl_up_sync(0x0000ffffu, x, o);
            if (t >= o) x += u;
        }
        ws[t] = x;
    }
    __syncthreads();
    int add = (w > 0) ? ws[w-1] : 0;
    if (t < nb) g_bsums[t] = add + inc;
}

__global__ void k_scan3(){
    int i = blockIdx.x*blockDim.x + threadIdx.x;
    if (i < RN){
        int g = i >> 10;
        if (g > 0) g_off[i] += g_bsums[g-1];
    }
}

__global__ void k_fill(const int* __restrict__ esrc, const int* __restrict__ edst){
    int i = blockIdx.x*blockDim.x + threadIdx.x;
    if (i < RE_TOT){
        int r = i / EE;
        int d = edst[i];
        int pos = atomicAdd(&g_cur[r*NN + d], 1);
        g_col[pos] = esrc[i];
    }
}

// ---------------- agg0: warp per node, gather fp16 embeds, write h fp16 ----------------
__global__ __launch_bounds__(256) void k_agg0(const __half* __restrict__ he,
                                              const float* __restrict__ ebias){
    int n = blockIdx.x*8 + (threadIdx.x >> 5);
    if (n >= NN) return;
    int lane = threadIdx.x & 31;
    float4 tot = {0.f,0.f,0.f,0.f};
    #pragma unroll 1
    for (int r = 0; r < RR; r++){
        int rn = r*NN + n;
        int s0 = g_off[rn];
        int dg = g_deg[rn];
        const __half* base = he + (size_t)r*NN*DD;
        float4 acc = {0.f,0.f,0.f,0.f};
        for (int bs = 0; bs < dg; bs += 32){
            int m = min(32, dg - bs);
            int cv = (lane < m) ? g_col[s0 + bs + lane] : 0;
            int j = 0;
            for (; j + 4 <= m; j += 4){
                int sa = __shfl_sync(0xffffffffu, cv, j);
                int sb = __shfl_sync(0xffffffffu, cv, j+1);
                int sc = __shfl_sync(0xffffffffu, cv, j+2);
                int sd = __shfl_sync(0xffffffffu, cv, j+3);
                uint2 v0 = reinterpret_cast<const uint2*>(base + (size_t)sa*DD)[lane];
                uint2 v1 = reinterpret_cast<const uint2*>(base + (size_t)sb*DD)[lane];
                uint2 v2 = reinterpret_cast<const uint2*>(base + (size_t)sc*DD)[lane];
                uint2 v3 = reinterpret_cast<const uint2*>(base + (size_t)sd*DD)[lane];
                float2 a0 = __half22float2(*(__half2*)&v0.x), b0 = __half22float2(*(__half2*)&v0.y);
                float2 a1 = __half22float2(*(__half2*)&v1.x), b1 = __half22float2(*(__half2*)&v1.y);
                float2 a2 = __half22float2(*(__half2*)&v2.x), b2 = __half22float2(*(__half2*)&v2.y);
                float2 a3 = __half22float2(*(__half2*)&v3.x), b3 = __half22float2(*(__half2*)&v3.y);
                acc.x += a0.x + a1.x + a2.x + a3.x;
                acc.y += a0.y + a1.y + a2.y + a3.y;
                acc.z += b0.x + b1.x + b2.x + b3.x;
                acc.w += b0.y + b1.y + b2.y + b3.y;
            }
            for (; j < m; j++){
                int s = __shfl_sync(0xffffffffu, cv, j);
                uint2 v = reinterpret_cast<const uint2*>(base + (size_t)s*DD)[lane];
                float2 a = __half22float2(*(__half2*)&v.x), b = __half22float2(*(__half2*)&v.y);
                acc.x += a.x; acc.y += a.y; acc.z += b.x; acc.w += b.y;
            }
        }
        float iv = g_inv[rn];
        tot.x += acc.x*iv; tot.y += acc.y*iv; tot.z += acc.z*iv; tot.w += acc.w*iv;
    }
    float4 bb = reinterpret_cast<const float4*>(ebias)[lane];
    __half2 p0 = __floats2half2_rn(fmaxf(tot.x + bb.x, 0.f), fmaxf(tot.y + bb.y, 0.f));
    __half2 p1 = __floats2half2_rn(fmaxf(tot.z + bb.z, 0.f), fmaxf(tot.w + bb.w, 0.f));
    uint2 st; st.x = *(uint32_t*)&p0; st.y = *(uint32_t*)&p1;
    reinterpret_cast<uint2*>(g_h + (size_t)n*DD)[lane] = st;
}

// ---------------- agg1: gather h fp16, per-basis combine, write M fp16 ----------------
__global__ __launch_bounds__(256) void k_agg1(const float* __restrict__ w1comp){
    int n = blockIdx.x*8 + (threadIdx.x >> 5);
    if (n >= NN) return;
    int lane = threadIdx.x & 31;
    float4 macc[4];
    #pragma unroll
    for (int b = 0; b < 4; b++) macc[b] = make_float4(0.f,0.f,0.f,0.f);
    #pragma unroll 1
    for (int r = 0; r < RR; r++){
        int rn = r*NN + n;
        int s0 = g_off[rn];
        int dg = g_deg[rn];
        float4 acc = {0.f,0.f,0.f,0.f};
        for (int bs = 0; bs < dg; bs += 32){
            int m = min(32, dg - bs);
            int cv = (lane < m) ? g_col[s0 + bs + lane] : 0;
            int j = 0;
            for (; j + 4 <= m; j += 4){
                int sa = __shfl_sync(0xffffffffu, cv, j);
                int sb = __shfl_sync(0xffffffffu, cv, j+1);
                int sc = __shfl_sync(0xffffffffu, cv, j+2);
                int sd = __shfl_sync(0xffffffffu, cv, j+3);
                uint2 v0 = reinterpret_cast<const uint2*>(g_h + (size_t)sa*DD)[lane];
                uint2 v1 = reinterpret_cast<const uint2*>(g_h + (size_t)sb*DD)[lane];
                uint2 v2 = reinterpret_cast<const uint2*>(g_h + (size_t)sc*DD)[lane];
                uint2 v3 = reinterpret_cast<const uint2*>(g_h + (size_t)sd*DD)[lane];
                float2 a0 = __half22float2(*(__half2*)&v0.x), b0 = __half22float2(*(__half2*)&v0.y);
                float2 a1 = __half22float2(*(__half2*)&v1.x), b1 = __half22float2(*(__half2*)&v1.y);
                float2 a2 = __half22float2(*(__half2*)&v2.x), b2 = __half22float2(*(__half2*)&v2.y);
                float2 a3 = __half22float2(*(__half2*)&v3.x), b3 = __half22float2(*(__half2*)&v3.y);
                acc.x += a0.x + a1.x + a2.x + a3.x;
                acc.y += a0.y + a1.y + a2.y + a3.y;
                acc.z += b0.x + b1.x + b2.x + b3.x;
                acc.w += b0.y + b1.y + b2.y + b3.y;
            }
            for (; j < m; j++){
                int s = __shfl_sync(0xffffffffu, cv, j);
                uint2 v = reinterpret_cast<const uint2*>(g_h + (size_t)s*DD)[lane];
                float2 a = __half22float2(*(__half2*)&v.x), b = __half22float2(*(__half2*)&v.y);
                acc.x += a.x; acc.y += a.y; acc.z += b.x; acc.w += b.y;
            }
        }
        float iv = g_inv[rn];
        #pragma unroll
        for (int b = 0; b < 4; b++){
            float w = w1comp[r*BB + b] * iv;
            macc[b].x += acc.x*w; macc[b].y += acc.y*w;
            macc[b].z += acc.z*w; macc[b].w += acc.w*w;
        }
    }
    #pragma unroll
    for (int b = 0; b < 4; b++){
        __half2 p0 = __floats2half2_rn(macc[b].x, macc[b].y);
        __half2 p1 = __floats2half2_rn(macc[b].z, macc[b].w);
        uint2 st; st.x = *(uint32_t*)&p0; st.y = *(uint32_t*)&p1;
        *reinterpret_cast<uint2*>(g_M + (size_t)n*512 + b*128 + lane*4) = st;
    }
}

// ---------------- B-fragment prep (fp32 -> fp16 mma fragment layout) ----------------
__device__ __forceinline__ uint32_t pk(float a, float b){
    __half2 h = __floats2half2_rn(a, b);
    return *(uint32_t*)&h;
}

__global__ void k_prepB(const float* __restrict__ w1b, const float* __restrict__ w2b){
    int i = blockIdx.x*blockDim.x + threadIdx.x;
    if (i < 32*16*32){
        int lane = i & 31, nt = (i >> 5) & 15, ks = i >> 9;
        int k0 = ks*16 + (lane & 3)*2;
        int n  = nt*8 + (lane >> 2);
        uint2 v;
        v.x = pk(w1b[(size_t)k0*128 + n],     w1b[(size_t)(k0+1)*128 + n]);
        v.y = pk(w1b[(size_t)(k0+8)*128 + n], w1b[(size_t)(k0+9)*128 + n]);
        g_Bf1[i] = v;
    } else if (i < 32*16*32 + 8*8*32){
        int ii = i - 32*16*32;
        int lane = ii & 31, nt = (ii >> 5) & 7, ks = ii >> 8;
        int k0 = ks*16 + (lane & 3)*2;
        int n  = nt*8 + (lane >> 2);
        int b = n >> 4, c = n & 15;
        uint2 v;
        v.x = pk(w2b[((size_t)b*128 + k0)*16 + c],   w2b[((size_t)b*128 + k0+1)*16 + c]);
        v.y = pk(w2b[((size_t)b*128 + k0+8)*16 + c], w2b[((size_t)b*128 + k0+9)*16 + c]);
        g_BfY[ii] = v;
    }
}

// ---------------- HMMA GEMM1: h1 = relu(M[N,512] @ B1[512,128] + b1) ----------------
__global__ __launch_bounds__(256) void k_hmma1(const __half* __restrict__ A,
                                               const uint2*  __restrict__ Bf,
                                               const float*  __restrict__ bias,
                                               __half* __restrict__ Cout){
    constexpr int KDIM = 512, NCOLS = 128, NTT = 16, KS = 32;
    int t = threadIdx.x;
    int lane = t & 31, w = t >> 5;
    int mrow = blockIdx.x*128 + w*16 + (lane >> 2);
    const __half* Arow0 = A + (size_t)mrow*KDIM;
    const __half* Arow1 = Arow0 + 8*KDIM;
    int klane = (lane & 3)*2;

    #pragma unroll 1
    for (int nh = 0; nh < 2; nh++){
        float c[8][4];
        #pragma unroll
        for (int nt = 0; nt < 8; nt++){ c[nt][0]=0.f; c[nt][1]=0.f; c[nt][2]=0.f; c[nt][3]=0.f; }
        #pragma unroll 4
        for (int ks = 0; ks < KS; ks++){
            int k0 = ks*16 + klane;
            uint32_t a0 = *(const uint32_t*)(Arow0 + k0);
            uint32_t a1 = *(const uint32_t*)(Arow1 + k0);
            uint32_t a2 = *(const uint32_t*)(Arow0 + k0 + 8);
            uint32_t a3 = *(const uint32_t*)(Arow1 + k0 + 8);
            const uint2* brow = Bf + ((size_t)ks*NTT + nh*8)*32 + lane;
            #pragma unroll
            for (int nt = 0; nt < 8; nt++){
                uint2 b = brow[nt*32];
                asm volatile(
                    "mma.sync.aligned.m16n8k16.row.col.f32.f16.f16.f32 "
                    "{%0,%1,%2,%3},{%4,%5,%6,%7},{%8,%9},{%0,%1,%2,%3};\n"
                    : "+f"(c[nt][0]), "+f"(c[nt][1]), "+f"(c[nt][2]), "+f"(c[nt][3])
                    : "r"(a0), "r"(a1), "r"(a2), "r"(a3), "r"(b.x), "r"(b.y));
            }
        }
        #pragma unroll
        for (int nt = 0; nt < 8; nt++){
            int col = nh*64 + nt*8 + klane;
            float bx = bias[col], by = bias[col+1];
            float v0 = fmaxf(c[nt][0] + bx, 0.f), v1 = fmaxf(c[nt][1] + by, 0.f);
            float v2 = fmaxf(c[nt][2] + bx, 0.f), v3 = fmaxf(c[nt][3] + by, 0.f);
            *(__half2*)(Cout + (size_t)mrow*NCOLS + col)     = __floats2half2_rn(v0, v1);
            *(__half2*)(Cout + (size_t)(mrow+8)*NCOLS + col) = __floats2half2_rn(v2, v3);
        }
    }
}

// ---------------- HMMA GEMM-Z: Z[n][r*16+c] = sum_b w2c[r,b]*(h1 @ basis_b)[n,c] ----------------
__global__ __launch_bounds__(256) void k_hmmaZ(const __half* __restrict__ A,
                                               const uint2*  __restrict__ Bf,
                                               const float*  __restrict__ w2comp,
                                               __half* __restrict__ Zout){
    constexpr int KDIM = 128, NTT = 8, KS = 8;
    int t = threadIdx.x;
    int lane = t & 31, w = t >> 5;
    int mrow = blockIdx.x*128 + w*16 + (lane >> 2);
    const __half* Arow0 = A + (size_t)mrow*KDIM;
    const __half* Arow1 = Arow0 + 8*KDIM;
    int klane = (lane & 3)*2;
    float wc[32];
    #pragma unroll
    for (int i = 0; i < 32; i++) wc[i] = w2comp[i];

    float c[8][4];
    #pragma unroll
    for (int nt = 0; nt < 8; nt++){ c[nt][0]=0.f; c[nt][1]=0.f; c[nt][2]=0.f; c[nt][3]=0.f; }
    #pragma unroll
    for (int ks = 0; ks < KS; ks++){
        int k0 = ks*16 + klane;
        uint32_t a0 = *(const uint32_t*)(Arow0 + k0);
        uint32_t a1 = *(const uint32_t*)(Arow1 + k0);
        uint32_t a2 = *(const uint32_t*)(Arow0 + k0 + 8);
        uint32_t a3 = *(const uint32_t*)(Arow1 + k0 + 8);
        const uint2* brow = Bf + (size_t)ks*NTT*32 + lane;
        #pragma unroll
        for (int nt = 0; nt < 8; nt++){
            uint2 b = brow[nt*32];
            asm volatile(
                "mma.sync.aligned.m16n8k16.row.col.f32.f16.f16.f32 "
                "{%0,%1,%2,%3},{%4,%5,%6,%7},{%8,%9},{%0,%1,%2,%3};\n"
                : "+f"(c[nt][0]), "+f"(c[nt][1]), "+f"(c[nt][2]), "+f"(c[nt][3])
                : "r"(a0), "r"(a1), "r"(a2), "r"(a3), "r"(b.x), "r"(b.y));
        }
    }
    // epilogue: Y col = nt*8 + klane + {0,1}; b = nt>>1; c16 = (nt&1)*8 + klane + {0,1}
    #pragma unroll
    for (int r = 0; r < 8; r++){
        #pragma unroll
        for (int pi = 0; pi < 2; pi++){
            float z00=0.f, z01=0.f, z10=0.f, z11=0.f;
            #pragma unroll
            for (int k = 0; k < 4; k++){
                float wv = wc[r*4 + k];
                z00 += wv*c[2*k+pi][0]; z01 += wv*c[2*k+pi][1];
                z10 += wv*c[2*k+pi][2]; z11 += wv*c[2*k+pi][3];
            }
            int cc = r*16 + pi*8 + klane;
            *(__half2*)(Zout + (size_t)mrow*128 + cc)     = __floats2half2_rn(z00, z01);
            *(__half2*)(Zout + (size_t)(mrow+8)*128 + cc) = __floats2half2_rn(z10, z11);
        }
    }
}

// ---------------- output aggregation over Z: out = b2 + sum_r inv_r * agg_r(Z[:,r*16:+16]) ----------------
__global__ __launch_bounds__(256) void k_agg2z(const float* __restrict__ b2,
                                               float* __restrict__ out){
    int n = blockIdx.x*8 + (threadIdx.x >> 5);
    if (n >= NN) return;
    int lane = threadIdx.x & 31;
    int e  = lane >> 1;     // edge slot 0..15
    int hh = lane & 1;      // column half (8 cols)
    float tot[8];
    #pragma unroll
    for (int k = 0; k < 8; k++) tot[k] = 0.f;
    #pragma unroll 1
    for (int r = 0; r < RR; r++){
        int rn = r*NN + n;
        int s0 = g_off[rn];
        int dg = g_deg[rn];
        float racc[8];
        #pragma unroll
        for (int k = 0; k < 8; k++) racc[k] = 0.f;
        for (int bs = 0; bs < dg; bs += 32){
            int m = min(32, dg - bs);
            int cv = (lane < m) ? g_col[s0 + bs + lane] : 0;
            #pragma unroll
            for (int hb = 0; hb < 2; hb++){
                int j = hb*16 + e;
                int s = __shfl_sync(0xffffffffu, cv, j);
                if (j < m){
                    uint4 v = *(const uint4*)(g_Z + (size_t)s*128 + r*16 + hh*8);
                    float2 f0 = __half22float2(*(__half2*)&v.x);
                    float2 f1 = __half22float2(*(__half2*)&v.y);
                    float2 f2 = __half22float2(*(__half2*)&v.z);
                    float2 f3 = __half22float2(*(__half2*)&v.w);
                    racc[0] += f0.x; racc[1] += f0.y; racc[2] += f1.x; racc[3] += f1.y;
                    racc[4] += f2.x; racc[5] += f2.y; racc[6] += f3.x; racc[7] += f3.y;
                }
            }
        }
        float iv = g_inv[rn];
        #pragma unroll
        for (int k = 0; k < 8; k++) tot[k] += racc[k]*iv;
    }
    // reduce over the 16 edge slots (keep hh groups separate: xor strides 2..16)
    #pragma unroll
    for (int off = 2; off < 32; off <<= 1){
        #pragma unroll
        for (int k = 0; k < 8; k++) tot[k] += __shfl_xor_sync(0xffffffffu, tot[k], off);
    }
    if (lane < 2){
        float4 o0, o1;
        o0.x = tot[0] + b2[hh*8+0]; o0.y = tot[1] + b2[hh*8+1];
        o0.z = tot[2] + b2[hh*8+2]; o0.w = tot[3] + b2[hh*8+3];
        o1.x = tot[4] + b2[hh*8+4]; o1.y = tot[5] + b2[hh*8+5];
        o1.z = tot[6] + b2[hh*8+6]; o1.w = tot[7] + b2[hh*8+7];
        *(float4*)(out + (size_t)n*CC + hh*8)     = o0;
        *(float4*)(out + (size_t)n*CC + hh*8 + 4) = o1;
    }
}

// ---------------- launch ----------------
extern "C" void kernel_launch(void* const* d_in, const int* in_sizes, int n_in,
                              void* d_out, int out_size){
    const int*   esrc   = (const int*)  d_in[0];
    const int*   edst   = (const int*)  d_in[1];
    const float* embeds = (const float*)d_in[2];
    const float* ebias  = (const float*)d_in[3];
    const float* w1b    = (const float*)d_in[4];
    const float* w1c    = (const float*)d_in[5];
    const float* b1     = (const float*)d_in[6];
    const float* w2b    = (const float*)d_in[7];
    const float* w2c    = (const float*)d_in[8];
    const float* b2     = (const float*)d_in[9];
    float* out = (float*)d_out;

    void *p_deg, *p_off, *p_cur, *p_M, *p_h1, *p_Z, *p_he, *p_Bf1, *p_BfY;
    cudaGetSymbolAddress(&p_deg, g_deg);
    cudaGetSymbolAddress(&p_off, g_off);
    cudaGetSymbolAddress(&p_cur, g_cur);
    cudaGetSymbolAddress(&p_M,   g_M);
    cudaGetSymbolAddress(&p_h1,  g_h1);
    cudaGetSymbolAddress(&p_Z,   g_Z);
    cudaGetSymbolAddress(&p_he,  g_he);
    cudaGetSymbolAddress(&p_Bf1, g_Bf1);
    cudaGetSymbolAddress(&p_BfY, g_BfY);

    const int scan_blocks = (RN + 1023) / 1024;   // 391

    cudaMemsetAsync(p_deg, 0, sizeof(int)*RN);
    k_deg   <<<(RE_TOT+255)/256, 256>>>(edst);
    k_scan1 <<<scan_blocks, 512>>>();
    k_scan2 <<<1, 512>>>(scan_blocks);
    k_scan3 <<<(RN+255)/256, 256>>>();
    cudaMemcpyAsync(p_cur, p_off, sizeof(int)*RN, cudaMemcpyDeviceToDevice);
    k_fill  <<<(RE_TOT+255)/256, 256>>>(esrc, edst);

    k_cvt   <<<(int)(((size_t)RR*NN*DD/4 + 255)/256), 256>>>(embeds);
    k_prepB <<<(32*16*32 + 8*8*32 + 255)/256, 256>>>(w1b, w2b);

    k_agg0  <<<(NN+7)/8, 256>>>((const __half*)p_he, ebias);
    k_agg1  <<<(NN+7)/8, 256>>>(w1c);
    k_hmma1 <<<391, 256>>>((const __half*)p_M,  (const uint2*)p_Bf1, b1, (__half*)p_h1);
    k_hmmaZ <<<391, 256>>>((const __half*)p_h1, (const uint2*)p_BfY, w2c, (__half*)p_Z);
    k_agg2z <<<(NN+7)/8, 256>>>(b2, out);
}